// round 3
// baseline (speedup 1.0000x reference)
#include <cuda_runtime.h>

#define NN 50000
#define EE 800000
#define DD 64
#define HH 128
#define NUM_TILES 12500   // EE / 64

// Scratch (device globals; no allocation allowed)
__device__ float g_preS[NN * HH];   // sender-side layer0 precompute (+b0)
__device__ float g_preR[NN * HH];   // receiver-side layer0 precompute
__device__ float g_agg[NN * DD];    // segment-sum accumulator

// ---------------------------------------------------------------------------
__global__ void zero_agg_kernel() {
    int i = blockIdx.x * blockDim.x + threadIdx.x;
    if (i < NN * DD) g_agg[i] = 0.0f;
}

// ---------------------------------------------------------------------------
// Per-node precompute: preS[n] = h_s[n]@W0[0:64] + h_d[n]@W0[128:192] + b0
//                      preR[n] = h_s[n]@W0[64:128] + h_d[n]@W0[192:256]
// W0 rows 0..255 staged in smem (128KB); 64 nodes per block, 512 threads.
__global__ __launch_bounds__(512) void node_pre_kernel(
    const float* __restrict__ h_s, const float* __restrict__ h_d,
    const float* __restrict__ W0, const float* __restrict__ b0)
{
    extern __shared__ float sm[];
    float* ws = sm;              // 256*128 = 32768 floats
    float* nd = sm + 32768;      // 64 * 132 (padded) = 8448 floats

    int tid = threadIdx.x;
    for (int i = tid; i < 8192; i += 512)
        ((float4*)ws)[i] = ((const float4*)W0)[i];

    int base = blockIdx.x * 64;
    for (int i = tid; i < 2048; i += 512) {
        int r = i >> 5, q = i & 31;          // row, float4-slot within 128 floats
        int n = base + r;
        float4 v = make_float4(0.f, 0.f, 0.f, 0.f);
        if (n < NN) {
            if (q < 16) v = ((const float4*)(h_s + (size_t)n * 64))[q];
            else        v = ((const float4*)(h_d + (size_t)n * 64))[q - 16];
        }
        *((float4*)(nd + r * 132 + q * 4)) = v;
    }
    __syncthreads();

    int ty = tid >> 4, tx = tid & 15;
    int c = tx * 8;
    int r0 = ty * 2;
    float accS[2][8], accR[2][8];
    #pragma unroll
    for (int i = 0; i < 2; i++)
        #pragma unroll
        for (int j = 0; j < 8; j++) { accS[i][j] = 0.f; accR[i][j] = 0.f; }

    #pragma unroll 4
    for (int k = 0; k < 64; k++) {
        float a0 = nd[r0 * 132 + k];
        float a1 = nd[r0 * 132 + 132 + k];
        float e0 = nd[r0 * 132 + 64 + k];
        float e1 = nd[r0 * 132 + 132 + 64 + k];
        float wsa[8], wra[8], wsb[8], wrb[8];
        *(float4*)&wsa[0] = *(float4*)(ws + k * 128 + c);
        *(float4*)&wsa[4] = *(float4*)(ws + k * 128 + c + 4);
        *(float4*)&wra[0] = *(float4*)(ws + (64 + k) * 128 + c);
        *(float4*)&wra[4] = *(float4*)(ws + (64 + k) * 128 + c + 4);
        *(float4*)&wsb[0] = *(float4*)(ws + (128 + k) * 128 + c);
        *(float4*)&wsb[4] = *(float4*)(ws + (128 + k) * 128 + c + 4);
        *(float4*)&wrb[0] = *(float4*)(ws + (192 + k) * 128 + c);
        *(float4*)&wrb[4] = *(float4*)(ws + (192 + k) * 128 + c + 4);
        #pragma unroll
        for (int j = 0; j < 8; j++) {
            accS[0][j] += a0 * wsa[j] + e0 * wsb[j];
            accS[1][j] += a1 * wsa[j] + e1 * wsb[j];
            accR[0][j] += a0 * wra[j] + e0 * wrb[j];
            accR[1][j] += a1 * wra[j] + e1 * wrb[j];
        }
    }

    float bv[8];
    *(float4*)&bv[0] = *(const float4*)(b0 + c);
    *(float4*)&bv[4] = *(const float4*)(b0 + c + 4);
    #pragma unroll
    for (int i = 0; i < 2; i++) {
        int n = base + r0 + i;
        if (n < NN) {
            #pragma unroll
            for (int j = 0; j < 8; j++) {
                g_preS[(size_t)n * 128 + c + j] = accS[i][j] + bv[j];
                g_preR[(size_t)n * 128 + c + j] = accR[i][j];
            }
        }
    }
}

// ---------------------------------------------------------------------------
// Persistent edge kernel. All weights resident in smem. 64 edges/tile.
// Layer0 init gathers preS[sender]+preR[receiver]; K-loop only over edge_feat.
__global__ __launch_bounds__(512) void edge_kernel(
    const float* __restrict__ edge_feat,
    const int* __restrict__ sender, const int* __restrict__ receiver,
    const float* __restrict__ h_d,
    const float* __restrict__ W0, const float* __restrict__ W1,
    const float* __restrict__ b1, const float* __restrict__ W2,
    const float* __restrict__ b2)
{
    extern __shared__ float sm[];
    float* w0e = sm;              //  8192  (W0 rows 256..319: edge_feat part)
    float* w1s = w0e + 8192;      // 16384
    float* w2s = w1s + 16384;     //  8192
    float* b1s = w2s + 8192;      //   128
    float* b2s = b1s + 128;       //    64
    float* ef  = b2s + 64;        //  64*68 = 4352
    float* x0  = ef + 4352;       //  64*132 = 8448
    float* x1  = x0 + 8448;       //  8448
    int* sidx  = (int*)(x1 + 8448);   // 64
    int* ridx  = sidx + 64;           // 64

    int tid = threadIdx.x;
    for (int i = tid; i < 2048; i += 512)
        ((float4*)w0e)[i] = ((const float4*)(W0 + 32768))[i];
    for (int i = tid; i < 4096; i += 512)
        ((float4*)w1s)[i] = ((const float4*)W1)[i];
    for (int i = tid; i < 2048; i += 512)
        ((float4*)w2s)[i] = ((const float4*)W2)[i];
    if (tid < 128)      b1s[tid] = b1[tid];
    else if (tid < 192) b2s[tid - 128] = b2[tid - 128];

    int ty = tid >> 4, tx = tid & 15;
    int c  = tx * 8;        // layer0/1 column start (of 128)
    int r0 = ty * 2;        // layer0/1 row start (2 rows each)
    int rl = tid >> 3;      // layer2 row (0..63)
    int c2 = (tid & 7) * 8; // layer2 column start (of 64)

    for (int tile = blockIdx.x; tile < NUM_TILES; tile += gridDim.x) {
        int ebase = tile * 64;
        __syncthreads();   // protect smem vs previous tile's readers
        if (tid < 64) { sidx[tid] = sender[ebase + tid]; ridx[tid] = receiver[ebase + tid]; }
        for (int i = tid; i < 1024; i += 512) {
            int r = i >> 4, q = i & 15;
            *((float4*)(ef + r * 68 + q * 4)) =
                ((const float4*)(edge_feat + (size_t)(ebase + r) * 64))[q];
        }
        __syncthreads();

        // ----- layer 0: acc = preS[s] + preR[r] (+b0 folded) + ef @ W0e -----
        float acc[2][8];
        #pragma unroll
        for (int i = 0; i < 2; i++) {
            int s = sidx[r0 + i], rr = ridx[r0 + i];
            float4 p0 = *(const float4*)(g_preS + (size_t)s * 128 + c);
            float4 p1 = *(const float4*)(g_preS + (size_t)s * 128 + c + 4);
            float4 q0 = *(const float4*)(g_preR + (size_t)rr * 128 + c);
            float4 q1 = *(const float4*)(g_preR + (size_t)rr * 128 + c + 4);
            acc[i][0] = p0.x + q0.x; acc[i][1] = p0.y + q0.y;
            acc[i][2] = p0.z + q0.z; acc[i][3] = p0.w + q0.w;
            acc[i][4] = p1.x + q1.x; acc[i][5] = p1.y + q1.y;
            acc[i][6] = p1.z + q1.z; acc[i][7] = p1.w + q1.w;
        }
        #pragma unroll 8
        for (int k = 0; k < 64; k++) {
            float a0 = ef[r0 * 68 + k];
            float a1 = ef[r0 * 68 + 68 + k];
            float w[8];
            *(float4*)&w[0] = *(float4*)(w0e + k * 128 + c);
            *(float4*)&w[4] = *(float4*)(w0e + k * 128 + c + 4);
            #pragma unroll
            for (int j = 0; j < 8; j++) { acc[0][j] += a0 * w[j]; acc[1][j] += a1 * w[j]; }
        }
        #pragma unroll
        for (int i = 0; i < 2; i++) {
            *((float4*)(x0 + (r0 + i) * 132 + c)) = make_float4(
                fmaxf(acc[i][0], 0.f), fmaxf(acc[i][1], 0.f),
                fmaxf(acc[i][2], 0.f), fmaxf(acc[i][3], 0.f));
            *((float4*)(x0 + (r0 + i) * 132 + c + 4)) = make_float4(
                fmaxf(acc[i][4], 0.f), fmaxf(acc[i][5], 0.f),
                fmaxf(acc[i][6], 0.f), fmaxf(acc[i][7], 0.f));
        }
        __syncthreads();

        // ----- layer 1 -----
        #pragma unroll
        for (int i = 0; i < 2; i++)
            #pragma unroll
            for (int j = 0; j < 8; j++) acc[i][j] = b1s[c + j];
        #pragma unroll 8
        for (int k = 0; k < 128; k++) {
            float a0 = x0[r0 * 132 + k];
            float a1 = x0[r0 * 132 + 132 + k];
            float w[8];
            *(float4*)&w[0] = *(float4*)(w1s + k * 128 + c);
            *(float4*)&w[4] = *(float4*)(w1s + k * 128 + c + 4);
            #pragma unroll
            for (int j = 0; j < 8; j++) { acc[0][j] += a0 * w[j]; acc[1][j] += a1 * w[j]; }
        }
        #pragma unroll
        for (int i = 0; i < 2; i++) {
            *((float4*)(x1 + (r0 + i) * 132 + c)) = make_float4(
                fmaxf(acc[i][0], 0.f), fmaxf(acc[i][1], 0.f),
                fmaxf(acc[i][2], 0.f), fmaxf(acc[i][3], 0.f));
            *((float4*)(x1 + (r0 + i) * 132 + c + 4)) = make_float4(
                fmaxf(acc[i][4], 0.f), fmaxf(acc[i][5], 0.f),
                fmaxf(acc[i][6], 0.f), fmaxf(acc[i][7], 0.f));
        }
        __syncthreads();

        // ----- layer 2 + epilogue: psi * (h_dj - h_di) -> atomic scatter -----
        float p[8];
        #pragma unroll
        for (int j = 0; j < 8; j++) p[j] = b2s[c2 + j];
        #pragma unroll 8
        for (int k = 0; k < 128; k++) {
            float a = x1[rl * 132 + k];
            float w[8];
            *(float4*)&w[0] = *(float4*)(w2s + k * 64 + c2);
            *(float4*)&w[4] = *(float4*)(w2s + k * 64 + c2 + 4);
            #pragma unroll
            for (int j = 0; j < 8; j++) p[j] += a * w[j];
        }
        int s = sidx[rl], rcv = ridx[rl];
        float4 hs0 = *(const float4*)(h_d + (size_t)s * 64 + c2);
        float4 hs1 = *(const float4*)(h_d + (size_t)s * 64 + c2 + 4);
        float4 hr0 = *(const float4*)(h_d + (size_t)rcv * 64 + c2);
        float4 hr1 = *(const float4*)(h_d + (size_t)rcv * 64 + c2 + 4);
        float dv[8] = { hr0.x - hs0.x, hr0.y - hs0.y, hr0.z - hs0.z, hr0.w - hs0.w,
                        hr1.x - hs1.x, hr1.y - hs1.y, hr1.z - hs1.z, hr1.w - hs1.w };
        float* aggp = g_agg + (size_t)rcv * 64 + c2;
        #pragma unroll
        for (int j = 0; j < 8; j++)
            atomicAdd(aggp + j, fmaxf(p[j], 0.f) * dv[j]);
    }
}

// ---------------------------------------------------------------------------
// out = h_d_prev + agg @ Wm
__global__ __launch_bounds__(256) void out_kernel(
    const float* __restrict__ h_d, const float* __restrict__ Wm,
    float* __restrict__ out)
{
    __shared__ float wm[4096];
    __shared__ float ag[64 * 68];
    int tid = threadIdx.x;
    for (int i = tid; i < 1024; i += 256)
        ((float4*)wm)[i] = ((const float4*)Wm)[i];
    int base = blockIdx.x * 64;
    for (int i = tid; i < 1024; i += 256) {
        int r = i >> 4, q = i & 15;
        int n = base + r;
        float4 v = make_float4(0.f, 0.f, 0.f, 0.f);
        if (n < NN) v = *((const float4*)(g_agg + (size_t)n * 64 + q * 4));
        *((float4*)(ag + r * 68 + q * 4)) = v;
    }
    __syncthreads();

    int row = tid >> 2;
    int cb = (tid & 3) * 16;
    float acc[16];
    #pragma unroll
    for (int j = 0; j < 16; j++) acc[j] = 0.f;
    #pragma unroll 8
    for (int k = 0; k < 64; k++) {
        float a = ag[row * 68 + k];
        float w[16];
        *(float4*)&w[0]  = *(float4*)(wm + k * 64 + cb);
        *(float4*)&w[4]  = *(float4*)(wm + k * 64 + cb + 4);
        *(float4*)&w[8]  = *(float4*)(wm + k * 64 + cb + 8);
        *(float4*)&w[12] = *(float4*)(wm + k * 64 + cb + 12);
        #pragma unroll
        for (int j = 0; j < 16; j++) acc[j] += a * w[j];
    }
    int n = base + row;
    if (n < NN) {
        #pragma unroll
        for (int v4 = 0; v4 < 4; v4++) {
            float4 h = *((const float4*)(h_d + (size_t)n * 64 + cb + v4 * 4));
            float4 o = make_float4(acc[v4 * 4 + 0] + h.x, acc[v4 * 4 + 1] + h.y,
                                   acc[v4 * 4 + 2] + h.z, acc[v4 * 4 + 3] + h.w);
            *((float4*)(out + (size_t)n * 64 + cb + v4 * 4)) = o;
        }
    }
}

// ---------------------------------------------------------------------------
#define NODE_SMEM ((32768 + 8448) * 4)                     // 164864 B
#define EDGE_SMEM ((8192 + 16384 + 8192 + 128 + 64 + 4352 + 8448 + 8448 + 128) * 4) // 217344 B

extern "C" void kernel_launch(void* const* d_in, const int* in_sizes, int n_in,
                              void* d_out, int out_size) {
    const float* h_d_prev  = (const float*)d_in[0];
    const float* h_s       = (const float*)d_in[1];
    const float* edge_feat = (const float*)d_in[2];
    const int*   sender    = (const int*)d_in[3];
    const int*   receiver  = (const int*)d_in[4];
    const float* W0        = (const float*)d_in[5];
    const float* b0        = (const float*)d_in[6];
    const float* W1        = (const float*)d_in[7];
    const float* b1        = (const float*)d_in[8];
    const float* W2        = (const float*)d_in[9];
    const float* b2        = (const float*)d_in[10];
    const float* Wm        = (const float*)d_in[11];
    float* out = (float*)d_out;

    (void)cudaFuncSetAttribute(node_pre_kernel,
                               cudaFuncAttributeMaxDynamicSharedMemorySize, NODE_SMEM);
    (void)cudaFuncSetAttribute(edge_kernel,
                               cudaFuncAttributeMaxDynamicSharedMemorySize, EDGE_SMEM);

    zero_agg_kernel<<<(NN * DD + 511) / 512, 512>>>();
    node_pre_kernel<<<(NN + 63) / 64, 512, NODE_SMEM>>>(h_s, h_d_prev, W0, b0);
    edge_kernel<<<148, 512, EDGE_SMEM>>>(edge_feat, sender, receiver, h_d_prev,
                                         W0, W1, b1, W2, b2);
    out_kernel<<<(NN + 63) / 64, 256>>>(h_d_prev, Wm, out);
}

// round 4
// speedup vs baseline: 1.6154x; 1.6154x over previous
#include <cuda_runtime.h>

#define NN 50000
#define EE 800000
#define DD 64
#define HH 128
#define TILE_E 128
#define NUM_TILES 6250    // EE / 128

// Scratch (device globals; no allocation allowed)
__device__ float g_preS[NN * HH];   // sender-side layer0 precompute (+b0)
__device__ float g_preR[NN * HH];   // receiver-side layer0 precompute
__device__ float g_agg[NN * DD];    // segment-sum accumulator

// ---------------------------------------------------------------------------
__global__ void zero_agg_kernel() {
    int i = blockIdx.x * blockDim.x + threadIdx.x;
    if (i < NN * DD) g_agg[i] = 0.0f;
}

// ---------------------------------------------------------------------------
// Per-node precompute: preS[n] = h_s[n]@W0[0:64] + h_d[n]@W0[128:192] + b0
//                      preR[n] = h_s[n]@W0[64:128] + h_d[n]@W0[192:256]
__global__ __launch_bounds__(512) void node_pre_kernel(
    const float* __restrict__ h_s, const float* __restrict__ h_d,
    const float* __restrict__ W0, const float* __restrict__ b0)
{
    extern __shared__ float sm[];
    float* ws = sm;              // 256*128 = 32768 floats
    float* nd = sm + 32768;      // 64 * 132 (padded) = 8448 floats

    int tid = threadIdx.x;
    for (int i = tid; i < 8192; i += 512)
        ((float4*)ws)[i] = ((const float4*)W0)[i];

    int base = blockIdx.x * 64;
    for (int i = tid; i < 2048; i += 512) {
        int r = i >> 5, q = i & 31;
        int n = base + r;
        float4 v = make_float4(0.f, 0.f, 0.f, 0.f);
        if (n < NN) {
            if (q < 16) v = ((const float4*)(h_s + (size_t)n * 64))[q];
            else        v = ((const float4*)(h_d + (size_t)n * 64))[q - 16];
        }
        *((float4*)(nd + r * 132 + q * 4)) = v;
    }
    __syncthreads();

    int ty = tid >> 4, tx = tid & 15;
    int c = tx * 8;
    int r0 = ty * 2;
    float accS[2][8], accR[2][8];
    #pragma unroll
    for (int i = 0; i < 2; i++)
        #pragma unroll
        for (int j = 0; j < 8; j++) { accS[i][j] = 0.f; accR[i][j] = 0.f; }

    #pragma unroll 4
    for (int k = 0; k < 64; k++) {
        float a0 = nd[r0 * 132 + k];
        float a1 = nd[r0 * 132 + 132 + k];
        float e0 = nd[r0 * 132 + 64 + k];
        float e1 = nd[r0 * 132 + 132 + 64 + k];
        float wsa[8], wra[8], wsb[8], wrb[8];
        *(float4*)&wsa[0] = *(float4*)(ws + k * 128 + c);
        *(float4*)&wsa[4] = *(float4*)(ws + k * 128 + c + 4);
        *(float4*)&wra[0] = *(float4*)(ws + (64 + k) * 128 + c);
        *(float4*)&wra[4] = *(float4*)(ws + (64 + k) * 128 + c + 4);
        *(float4*)&wsb[0] = *(float4*)(ws + (128 + k) * 128 + c);
        *(float4*)&wsb[4] = *(float4*)(ws + (128 + k) * 128 + c + 4);
        *(float4*)&wrb[0] = *(float4*)(ws + (192 + k) * 128 + c);
        *(float4*)&wrb[4] = *(float4*)(ws + (192 + k) * 128 + c + 4);
        #pragma unroll
        for (int j = 0; j < 8; j++) {
            accS[0][j] += a0 * wsa[j] + e0 * wsb[j];
            accS[1][j] += a1 * wsa[j] + e1 * wsb[j];
            accR[0][j] += a0 * wra[j] + e0 * wrb[j];
            accR[1][j] += a1 * wra[j] + e1 * wrb[j];
        }
    }

    float bv[8];
    *(float4*)&bv[0] = *(const float4*)(b0 + c);
    *(float4*)&bv[4] = *(const float4*)(b0 + c + 4);
    #pragma unroll
    for (int i = 0; i < 2; i++) {
        int n = base + r0 + i;
        if (n < NN) {
            #pragma unroll
            for (int j = 0; j < 8; j++) {
                g_preS[(size_t)n * 128 + c + j] = accS[i][j] + bv[j];
                g_preR[(size_t)n * 128 + c + j] = accR[i][j];
            }
        }
    }
}

// ---------------------------------------------------------------------------
// Persistent edge kernel. 128 edges/tile, 512 threads, 4x8 micro-tiles.
// Single activation buffer (stride 132): ef -> x0 -> x1, overwritten in place
// after register accumulation + barrier.
__global__ __launch_bounds__(512) void edge_kernel(
    const float* __restrict__ edge_feat,
    const int* __restrict__ sender, const int* __restrict__ receiver,
    const float* __restrict__ h_d,
    const float* __restrict__ W0, const float* __restrict__ W1,
    const float* __restrict__ b1, const float* __restrict__ W2,
    const float* __restrict__ b2)
{
    extern __shared__ float sm[];
    float* w0e = sm;               //  8192  (W0 rows 256..319)
    float* w1s = w0e + 8192;       // 16384
    float* w2s = w1s + 16384;      //  8192
    float* b1s = w2s + 8192;       //   128
    float* b2s = b1s + 128;        //    64
    float* buf = b2s + 64;         // 16896  (128 rows x stride 132)
    int* sidx  = (int*)(buf + 16896);  // 128
    int* ridx  = sidx + 128;           // 128

    int tid = threadIdx.x;
    for (int i = tid; i < 2048; i += 512)
        ((float4*)w0e)[i] = ((const float4*)(W0 + 32768))[i];
    for (int i = tid; i < 4096; i += 512)
        ((float4*)w1s)[i] = ((const float4*)W1)[i];
    for (int i = tid; i < 2048; i += 512)
        ((float4*)w2s)[i] = ((const float4*)W2)[i];
    if (tid < 128)      b1s[tid] = b1[tid];
    else if (tid < 192) b2s[tid - 128] = b2[tid - 128];

    int tx = tid & 15, ty = tid >> 4;
    int c  = tx * 8;        // col start (of 128) for layers 0/1
    int r0 = ty * 4;        // row start (4 rows of 128 edges)
    int e20 = (tid >> 3) * 2;   // layer2: 2 rows
    int c2  = (tid & 7) * 8;    // layer2: 8 cols (of 64)

    for (int tile = blockIdx.x; tile < NUM_TILES; tile += gridDim.x) {
        int ebase = tile * TILE_E;
        __syncthreads();   // buf free of previous tile's readers
        if (tid < 128) { sidx[tid] = sender[ebase + tid]; ridx[tid] = receiver[ebase + tid]; }
        for (int i = tid; i < 2048; i += 512) {
            int r = i >> 4, q = i & 15;
            *((float4*)(buf + r * 132 + q * 4)) =
                ((const float4*)(edge_feat + (size_t)(ebase + r) * 64))[q];
        }
        __syncthreads();

        // ----- layer 0: acc = preS[s] + preR[r] (b0 folded) + ef @ W0e -----
        float acc[4][8];
        #pragma unroll
        for (int i = 0; i < 4; i++) {
            int s = sidx[r0 + i], rr = ridx[r0 + i];
            float4 p0 = *(const float4*)(g_preS + (size_t)s * 128 + c);
            float4 p1 = *(const float4*)(g_preS + (size_t)s * 128 + c + 4);
            float4 q0 = *(const float4*)(g_preR + (size_t)rr * 128 + c);
            float4 q1 = *(const float4*)(g_preR + (size_t)rr * 128 + c + 4);
            acc[i][0] = p0.x + q0.x; acc[i][1] = p0.y + q0.y;
            acc[i][2] = p0.z + q0.z; acc[i][3] = p0.w + q0.w;
            acc[i][4] = p1.x + q1.x; acc[i][5] = p1.y + q1.y;
            acc[i][6] = p1.z + q1.z; acc[i][7] = p1.w + q1.w;
        }
        #pragma unroll 4
        for (int kb = 0; kb < 16; kb++) {
            float4 av[4];
            #pragma unroll
            for (int i = 0; i < 4; i++)
                av[i] = *(float4*)(buf + (r0 + i) * 132 + kb * 4);
            #pragma unroll
            for (int kk = 0; kk < 4; kk++) {
                int k = kb * 4 + kk;
                float w[8];
                *(float4*)&w[0] = *(float4*)(w0e + k * 128 + c);
                *(float4*)&w[4] = *(float4*)(w0e + k * 128 + c + 4);
                float a0 = ((float*)&av[0])[kk];
                float a1 = ((float*)&av[1])[kk];
                float a2 = ((float*)&av[2])[kk];
                float a3 = ((float*)&av[3])[kk];
                #pragma unroll
                for (int j = 0; j < 8; j++) {
                    acc[0][j] += a0 * w[j]; acc[1][j] += a1 * w[j];
                    acc[2][j] += a2 * w[j]; acc[3][j] += a3 * w[j];
                }
            }
        }
        __syncthreads();   // all ef reads complete
        #pragma unroll
        for (int i = 0; i < 4; i++) {
            *((float4*)(buf + (r0 + i) * 132 + c)) = make_float4(
                fmaxf(acc[i][0], 0.f), fmaxf(acc[i][1], 0.f),
                fmaxf(acc[i][2], 0.f), fmaxf(acc[i][3], 0.f));
            *((float4*)(buf + (r0 + i) * 132 + c + 4)) = make_float4(
                fmaxf(acc[i][4], 0.f), fmaxf(acc[i][5], 0.f),
                fmaxf(acc[i][6], 0.f), fmaxf(acc[i][7], 0.f));
        }
        __syncthreads();

        // ----- layer 1 (reads x0 from buf, overwrites in place) -----
        #pragma unroll
        for (int i = 0; i < 4; i++)
            #pragma unroll
            for (int j = 0; j < 8; j++) acc[i][j] = b1s[c + j];
        #pragma unroll 4
        for (int kb = 0; kb < 32; kb++) {
            float4 av[4];
            #pragma unroll
            for (int i = 0; i < 4; i++)
                av[i] = *(float4*)(buf + (r0 + i) * 132 + kb * 4);
            #pragma unroll
            for (int kk = 0; kk < 4; kk++) {
                int k = kb * 4 + kk;
                float w[8];
                *(float4*)&w[0] = *(float4*)(w1s + k * 128 + c);
                *(float4*)&w[4] = *(float4*)(w1s + k * 128 + c + 4);
                float a0 = ((float*)&av[0])[kk];
                float a1 = ((float*)&av[1])[kk];
                float a2 = ((float*)&av[2])[kk];
                float a3 = ((float*)&av[3])[kk];
                #pragma unroll
                for (int j = 0; j < 8; j++) {
                    acc[0][j] += a0 * w[j]; acc[1][j] += a1 * w[j];
                    acc[2][j] += a2 * w[j]; acc[3][j] += a3 * w[j];
                }
            }
        }
        __syncthreads();   // all x0 reads complete
        #pragma unroll
        for (int i = 0; i < 4; i++) {
            *((float4*)(buf + (r0 + i) * 132 + c)) = make_float4(
                fmaxf(acc[i][0], 0.f), fmaxf(acc[i][1], 0.f),
                fmaxf(acc[i][2], 0.f), fmaxf(acc[i][3], 0.f));
            *((float4*)(buf + (r0 + i) * 132 + c + 4)) = make_float4(
                fmaxf(acc[i][4], 0.f), fmaxf(acc[i][5], 0.f),
                fmaxf(acc[i][6], 0.f), fmaxf(acc[i][7], 0.f));
        }
        __syncthreads();

        // ----- layer 2 + epilogue: psi * (h_dj - h_di) -> atomic scatter -----
        float p[2][8];
        #pragma unroll
        for (int i = 0; i < 2; i++)
            #pragma unroll
            for (int j = 0; j < 8; j++) p[i][j] = b2s[c2 + j];
        #pragma unroll 4
        for (int kb = 0; kb < 32; kb++) {
            float4 av0 = *(float4*)(buf + e20 * 132 + kb * 4);
            float4 av1 = *(float4*)(buf + (e20 + 1) * 132 + kb * 4);
            #pragma unroll
            for (int kk = 0; kk < 4; kk++) {
                int k = kb * 4 + kk;
                float w[8];
                *(float4*)&w[0] = *(float4*)(w2s + k * 64 + c2);
                *(float4*)&w[4] = *(float4*)(w2s + k * 64 + c2 + 4);
                float a0 = ((float*)&av0)[kk];
                float a1 = ((float*)&av1)[kk];
                #pragma unroll
                for (int j = 0; j < 8; j++) {
                    p[0][j] += a0 * w[j]; p[1][j] += a1 * w[j];
                }
            }
        }
        #pragma unroll
        for (int i = 0; i < 2; i++) {
            int s = sidx[e20 + i], rcv = ridx[e20 + i];
            float4 hs0 = *(const float4*)(h_d + (size_t)s * 64 + c2);
            float4 hs1 = *(const float4*)(h_d + (size_t)s * 64 + c2 + 4);
            float4 hr0 = *(const float4*)(h_d + (size_t)rcv * 64 + c2);
            float4 hr1 = *(const float4*)(h_d + (size_t)rcv * 64 + c2 + 4);
            float dv[8] = { hr0.x - hs0.x, hr0.y - hs0.y, hr0.z - hs0.z, hr0.w - hs0.w,
                            hr1.x - hs1.x, hr1.y - hs1.y, hr1.z - hs1.z, hr1.w - hs1.w };
            float* aggp = g_agg + (size_t)rcv * 64 + c2;
            #pragma unroll
            for (int j = 0; j < 8; j++)
                atomicAdd(aggp + j, fmaxf(p[i][j], 0.f) * dv[j]);
        }
    }
}

// ---------------------------------------------------------------------------
// out = h_d_prev + agg @ Wm
__global__ __launch_bounds__(256) void out_kernel(
    const float* __restrict__ h_d, const float* __restrict__ Wm,
    float* __restrict__ out)
{
    __shared__ float wm[4096];
    __shared__ float ag[64 * 68];
    int tid = threadIdx.x;
    for (int i = tid; i < 1024; i += 256)
        ((float4*)wm)[i] = ((const float4*)Wm)[i];
    int base = blockIdx.x * 64;
    for (int i = tid; i < 1024; i += 256) {
        int r = i >> 4, q = i & 15;
        int n = base + r;
        float4 v = make_float4(0.f, 0.f, 0.f, 0.f);
        if (n < NN) v = *((const float4*)(g_agg + (size_t)n * 64 + q * 4));
        *((float4*)(ag + r * 68 + q * 4)) = v;
    }
    __syncthreads();

    int row = tid >> 2;
    int cb = (tid & 3) * 16;
    float acc[16];
    #pragma unroll
    for (int j = 0; j < 16; j++) acc[j] = 0.f;
    #pragma unroll 8
    for (int k = 0; k < 64; k++) {
        float a = ag[row * 68 + k];
        float w[16];
        *(float4*)&w[0]  = *(float4*)(wm + k * 64 + cb);
        *(float4*)&w[4]  = *(float4*)(wm + k * 64 + cb + 4);
        *(float4*)&w[8]  = *(float4*)(wm + k * 64 + cb + 8);
        *(float4*)&w[12] = *(float4*)(wm + k * 64 + cb + 12);
        #pragma unroll
        for (int j = 0; j < 16; j++) acc[j] += a * w[j];
    }
    int n = base + row;
    if (n < NN) {
        #pragma unroll
        for (int v4 = 0; v4 < 4; v4++) {
            float4 h = *((const float4*)(h_d + (size_t)n * 64 + cb + v4 * 4));
            float4 o = make_float4(acc[v4 * 4 + 0] + h.x, acc[v4 * 4 + 1] + h.y,
                                   acc[v4 * 4 + 2] + h.z, acc[v4 * 4 + 3] + h.w);
            *((float4*)(out + (size_t)n * 64 + cb + v4 * 4)) = o;
        }
    }
}

// ---------------------------------------------------------------------------
#define NODE_SMEM ((32768 + 8448) * 4)                                  // 164864 B
#define EDGE_SMEM ((8192 + 16384 + 8192 + 128 + 64 + 16896 + 256) * 4)  // 200448 B

extern "C" void kernel_launch(void* const* d_in, const int* in_sizes, int n_in,
                              void* d_out, int out_size) {
    const float* h_d_prev  = (const float*)d_in[0];
    const float* h_s       = (const float*)d_in[1];
    const float* edge_feat = (const float*)d_in[2];
    const int*   sender    = (const int*)d_in[3];
    const int*   receiver  = (const int*)d_in[4];
    const float* W0        = (const float*)d_in[5];
    const float* b0        = (const float*)d_in[6];
    const float* W1        = (const float*)d_in[7];
    const float* b1        = (const float*)d_in[8];
    const float* W2        = (const float*)d_in[9];
    const float* b2        = (const float*)d_in[10];
    const float* Wm        = (const float*)d_in[11];
    float* out = (float*)d_out;

    (void)cudaFuncSetAttribute(node_pre_kernel,
                               cudaFuncAttributeMaxDynamicSharedMemorySize, NODE_SMEM);
    (void)cudaFuncSetAttribute(edge_kernel,
                               cudaFuncAttributeMaxDynamicSharedMemorySize, EDGE_SMEM);

    zero_agg_kernel<<<(NN * DD + 511) / 512, 512>>>();
    node_pre_kernel<<<(NN + 63) / 64, 512, NODE_SMEM>>>(h_s, h_d_prev, W0, b0);
    edge_kernel<<<148, 512, EDGE_SMEM>>>(edge_feat, sender, receiver, h_d_prev,
                                         W0, W1, b1, W2, b2);
    out_kernel<<<(NN + 63) / 64, 256>>>(h_d_prev, Wm, out);
}

// round 7
// speedup vs baseline: 4.9641x; 3.0729x over previous
#include <cuda_runtime.h>
#include <cuda_bf16.h>
#include <cstdint>

#define NN 50000
#define EE 800000
#define NWT 50000   // EE / 16 edges per warp-tile

// Scratch (device globals; no allocation allowed)
__device__ float g_preS[NN * 128];  // sender-side layer0 precompute (+b0)
__device__ float g_preR[NN * 128];  // receiver-side layer0 precompute
__device__ float g_agg[NN * 64];    // segment-sum accumulator

// ---------------------------------------------------------------------------
__device__ __forceinline__ float relu(float x) { return fmaxf(x, 0.f); }

// bf16 hi/lo split of a float pair -> packed bf16x2 (low half = first elem)
__device__ __forceinline__ void split2(float x, float y, uint32_t& hi, uint32_t& lo) {
    __nv_bfloat162 h = __floats2bfloat162_rn(x, y);
    float hx = __bfloat162float(h.x);
    float hy = __bfloat162float(h.y);
    __nv_bfloat162 l = __floats2bfloat162_rn(x - hx, y - hy);
    hi = *reinterpret_cast<uint32_t*>(&h);
    lo = *reinterpret_cast<uint32_t*>(&l);
}

__device__ __forceinline__ void mma_bf16(float (&c)[4],
                                         uint32_t a0, uint32_t a1, uint32_t a2, uint32_t a3,
                                         uint32_t b0, uint32_t b1) {
    asm volatile(
        "mma.sync.aligned.m16n8k16.row.col.f32.bf16.bf16.f32 "
        "{%0,%1,%2,%3}, {%4,%5,%6,%7}, {%8,%9}, {%0,%1,%2,%3};"
        : "+f"(c[0]), "+f"(c[1]), "+f"(c[2]), "+f"(c[3])
        : "r"(a0), "r"(a1), "r"(a2), "r"(a3), "r"(b0), "r"(b1));
}

// Pack one B fragment (n8k16, col layout) for reading lane l of frag f.
__device__ __forceinline__ void pack_frag(const float* __restrict__ W, int ld,
                                          int k0, int n, uint2* hi, uint2* lo, int idx) {
    float w00 = W[(size_t)k0 * ld + n];
    float w01 = W[(size_t)(k0 + 1) * ld + n];
    float w10 = W[(size_t)(k0 + 8) * ld + n];
    float w11 = W[(size_t)(k0 + 9) * ld + n];
    uint32_t h0, l0, h1, l1;
    split2(w00, w01, h0, l0);
    split2(w10, w11, h1, l1);
    hi[idx] = make_uint2(h0, h1);
    lo[idx] = make_uint2(l0, l1);
}

// smem layout (uint2 units): W0H[2048] W0L[2048] W1H[4096] W1L[4096] W2H[2048] W2L[2048]
// then floats: b1[128] b2[64]
#define EDGE_SMEM (16384 * 8 + 768)   // 131840 B

// ---------------------------------------------------------------------------
__global__ void zero_agg_kernel() {
    int i = blockIdx.x * blockDim.x + threadIdx.x;
    if (i < NN * 64) g_agg[i] = 0.0f;
}

// ---------------------------------------------------------------------------
// Per-node precompute (fp32): preS = h_s@W0[0:64] + h_d@W0[128:192] + b0
//                             preR = h_s@W0[64:128] + h_d@W0[192:256]
__global__ __launch_bounds__(512) void node_pre_kernel(
    const float* __restrict__ h_s, const float* __restrict__ h_d,
    const float* __restrict__ W0, const float* __restrict__ b0)
{
    extern __shared__ float sm[];
    float* ws = sm;
    float* nd = sm + 32768;

    int tid = threadIdx.x;
    for (int i = tid; i < 8192; i += 512)
        ((float4*)ws)[i] = ((const float4*)W0)[i];

    int base = blockIdx.x * 64;
    for (int i = tid; i < 2048; i += 512) {
        int r = i >> 5, q = i & 31;
        int n = base + r;
        float4 v = make_float4(0.f, 0.f, 0.f, 0.f);
        if (n < NN) {
            if (q < 16) v = ((const float4*)(h_s + (size_t)n * 64))[q];
            else        v = ((const float4*)(h_d + (size_t)n * 64))[q - 16];
        }
        *((float4*)(nd + r * 132 + q * 4)) = v;
    }
    __syncthreads();

    int ty = tid >> 4, tx = tid & 15;
    int c = tx * 8;
    int r0 = ty * 2;
    float accS[2][8], accR[2][8];
    #pragma unroll
    for (int i = 0; i < 2; i++)
        #pragma unroll
        for (int j = 0; j < 8; j++) { accS[i][j] = 0.f; accR[i][j] = 0.f; }

    #pragma unroll 4
    for (int k = 0; k < 64; k++) {
        float a0 = nd[r0 * 132 + k];
        float a1 = nd[r0 * 132 + 132 + k];
        float e0 = nd[r0 * 132 + 64 + k];
        float e1 = nd[r0 * 132 + 132 + 64 + k];
        float wsa[8], wra[8], wsb[8], wrb[8];
        *(float4*)&wsa[0] = *(float4*)(ws + k * 128 + c);
        *(float4*)&wsa[4] = *(float4*)(ws + k * 128 + c + 4);
        *(float4*)&wra[0] = *(float4*)(ws + (64 + k) * 128 + c);
        *(float4*)&wra[4] = *(float4*)(ws + (64 + k) * 128 + c + 4);
        *(float4*)&wsb[0] = *(float4*)(ws + (128 + k) * 128 + c);
        *(float4*)&wsb[4] = *(float4*)(ws + (128 + k) * 128 + c + 4);
        *(float4*)&wrb[0] = *(float4*)(ws + (192 + k) * 128 + c);
        *(float4*)&wrb[4] = *(float4*)(ws + (192 + k) * 128 + c + 4);
        #pragma unroll
        for (int j = 0; j < 8; j++) {
            accS[0][j] += a0 * wsa[j] + e0 * wsb[j];
            accS[1][j] += a1 * wsa[j] + e1 * wsb[j];
            accR[0][j] += a0 * wra[j] + e0 * wrb[j];
            accR[1][j] += a1 * wra[j] + e1 * wrb[j];
        }
    }

    float bv[8];
    *(float4*)&bv[0] = *(const float4*)(b0 + c);
    *(float4*)&bv[4] = *(const float4*)(b0 + c + 4);
    #pragma unroll
    for (int i = 0; i < 2; i++) {
        int n = base + r0 + i;
        if (n < NN) {
            #pragma unroll
            for (int j = 0; j < 8; j++) {
                g_preS[(size_t)n * 128 + c + j] = accS[i][j] + bv[j];
                g_preR[(size_t)n * 128 + c + j] = accR[i][j];
            }
        }
    }
}

// ---------------------------------------------------------------------------
// Warp-autonomous HMMA edge kernel: each warp processes 16 edges via
// m16n8k16 bf16 mma.sync with hi/lo split; activations stay in registers.
__global__ __launch_bounds__(256, 1) void edge_kernel(
    const float* __restrict__ edge_feat,
    const int* __restrict__ sender, const int* __restrict__ receiver,
    const float* __restrict__ h_d,
    const float* __restrict__ W0, const float* __restrict__ W1,
    const float* __restrict__ b1, const float* __restrict__ W2,
    const float* __restrict__ b2)
{
    extern __shared__ unsigned char smraw[];
    uint2* W0H = (uint2*)smraw;        // 2048
    uint2* W0L = W0H + 2048;
    uint2* W1H = W0L + 2048;           // 4096
    uint2* W1L = W1H + 4096;
    uint2* W2H = W1L + 4096;           // 2048
    uint2* W2L = W2H + 2048;
    float* b1s = (float*)(W2L + 2048); // 128
    float* b2s = b1s + 128;            // 64

    int tid = threadIdx.x, wid = tid >> 5, lane = tid & 31;
    int q = lane & 3, g = lane >> 2;

    // ---- one-time fragment prepack ----
    for (int i = tid; i < 2048; i += 256) {          // W0e: 64 frags (s=f>>4, j=f&15)
        int f = i >> 5, l = i & 31;
        int s = f >> 4, j = f & 15;
        pack_frag(W0 + 256 * 128, 128, 16 * s + (l & 3) * 2, 8 * j + (l >> 2), W0H, W0L, i);
    }
    for (int i = tid; i < 4096; i += 256) {          // W1: 128 frags (s=f>>4, j=f&15)
        int f = i >> 5, l = i & 31;
        int s = f >> 4, j = f & 15;
        pack_frag(W1, 128, 16 * s + (l & 3) * 2, 8 * j + (l >> 2), W1H, W1L, i);
    }
    for (int i = tid; i < 2048; i += 256) {          // W2: 64 frags (s=f>>3, j=f&7)
        int f = i >> 5, l = i & 31;
        int s = f >> 3, j = f & 7;
        pack_frag(W2, 64, 16 * s + (l & 3) * 2, 8 * j + (l >> 2), W2H, W2L, i);
    }
    if (tid < 128) b1s[tid] = b1[tid];
    if (tid < 64)  b2s[tid] = b2[tid];
    __syncthreads();

    for (int wt = blockIdx.x * 8 + wid; wt < NWT; wt += gridDim.x * 8) {
        int ebase = wt * 16;
        int r0 = ebase + g, r1 = r0 + 8;
        int s0 = sender[r0],   s1 = sender[r1];
        int rc0 = receiver[r0], rc1 = receiver[r1];

        // ---- layer 0 C init: preS[s] + preR[rc]  (b0 folded in preS) ----
        float c0[16][4];
        {
            const float* pS0 = g_preS + (size_t)s0 * 128 + 2 * q;
            const float* pS1 = g_preS + (size_t)s1 * 128 + 2 * q;
            const float* pR0 = g_preR + (size_t)rc0 * 128 + 2 * q;
            const float* pR1 = g_preR + (size_t)rc1 * 128 + 2 * q;
            #pragma unroll
            for (int j = 0; j < 16; j++) {
                float2 a = *(const float2*)(pS0 + 8 * j);
                float2 b = *(const float2*)(pR0 + 8 * j);
                float2 e = *(const float2*)(pS1 + 8 * j);
                float2 d = *(const float2*)(pR1 + 8 * j);
                c0[j][0] = a.x + b.x; c0[j][1] = a.y + b.y;
                c0[j][2] = e.x + d.x; c0[j][3] = e.y + d.y;
            }
        }

        // ---- layer 0 mma: C += ef[16,64] @ W0e[64,128] ----
        {
            const float* e0p = edge_feat + (size_t)r0 * 64 + 2 * q;
            const float* e1p = edge_feat + (size_t)r1 * 64 + 2 * q;
            #pragma unroll
            for (int s = 0; s < 4; s++) {
                float2 ea = *(const float2*)(e0p + 16 * s);
                float2 eb = *(const float2*)(e0p + 16 * s + 8);
                float2 ec = *(const float2*)(e1p + 16 * s);
                float2 ed = *(const float2*)(e1p + 16 * s + 8);
                uint32_t ah[4], al[4];
                split2(ea.x, ea.y, ah[0], al[0]);
                split2(ec.x, ec.y, ah[1], al[1]);
                split2(eb.x, eb.y, ah[2], al[2]);
                split2(ed.x, ed.y, ah[3], al[3]);
                #pragma unroll
                for (int j = 0; j < 16; j++) {
                    uint2 bh = W0H[(s * 16 + j) * 32 + lane];
                    uint2 bl = W0L[(s * 16 + j) * 32 + lane];
                    mma_bf16(c0[j], ah[0], ah[1], ah[2], ah[3], bh.x, bh.y);
                    mma_bf16(c0[j], ah[0], ah[1], ah[2], ah[3], bl.x, bl.y);
                    mma_bf16(c0[j], al[0], al[1], al[2], al[3], bh.x, bh.y);
                }
            }
        }

        // ---- layer 1: C1 = relu(C0) @ W1 + b1 ----
        float c1[16][4];
        #pragma unroll
        for (int j = 0; j < 16; j++) {
            float2 bb = *(const float2*)(b1s + 8 * j + 2 * q);
            c1[j][0] = bb.x; c1[j][1] = bb.y; c1[j][2] = bb.x; c1[j][3] = bb.y;
        }
        #pragma unroll
        for (int s = 0; s < 8; s++) {
            uint32_t ah[4], al[4];
            split2(relu(c0[2 * s][0]),     relu(c0[2 * s][1]),     ah[0], al[0]);
            split2(relu(c0[2 * s][2]),     relu(c0[2 * s][3]),     ah[1], al[1]);
            split2(relu(c0[2 * s + 1][0]), relu(c0[2 * s + 1][1]), ah[2], al[2]);
            split2(relu(c0[2 * s + 1][2]), relu(c0[2 * s + 1][3]), ah[3], al[3]);
            #pragma unroll
            for (int j = 0; j < 16; j++) {
                uint2 bh = W1H[(s * 16 + j) * 32 + lane];
                uint2 bl = W1L[(s * 16 + j) * 32 + lane];
                mma_bf16(c1[j], ah[0], ah[1], ah[2], ah[3], bh.x, bh.y);
                mma_bf16(c1[j], ah[0], ah[1], ah[2], ah[3], bl.x, bl.y);
                mma_bf16(c1[j], al[0], al[1], al[2], al[3], bh.x, bh.y);
            }
        }

        // ---- layer 2: C2 = relu(C1) @ W2 + b2 ----
        float c2[8][4];
        #pragma unroll
        for (int j = 0; j < 8; j++) {
            float2 bb = *(const float2*)(b2s + 8 * j + 2 * q);
            c2[j][0] = bb.x; c2[j][1] = bb.y; c2[j][2] = bb.x; c2[j][3] = bb.y;
        }
        #pragma unroll
        for (int s = 0; s < 8; s++) {
            uint32_t ah[4], al[4];
            split2(relu(c1[2 * s][0]),     relu(c1[2 * s][1]),     ah[0], al[0]);
            split2(relu(c1[2 * s][2]),     relu(c1[2 * s][3]),     ah[1], al[1]);
            split2(relu(c1[2 * s + 1][0]), relu(c1[2 * s + 1][1]), ah[2], al[2]);
            split2(relu(c1[2 * s + 1][2]), relu(c1[2 * s + 1][3]), ah[3], al[3]);
            #pragma unroll
            for (int j = 0; j < 8; j++) {
                uint2 bh = W2H[(s * 8 + j) * 32 + lane];
                uint2 bl = W2L[(s * 8 + j) * 32 + lane];
                mma_bf16(c2[j], ah[0], ah[1], ah[2], ah[3], bh.x, bh.y);
                mma_bf16(c2[j], ah[0], ah[1], ah[2], ah[3], bl.x, bl.y);
                mma_bf16(c2[j], al[0], al[1], al[2], al[3], bh.x, bh.y);
            }
        }

        // ---- epilogue: psi = relu(C2); scatter psi * (h_dj - h_di) ----
        {
            const float* hs0 = h_d + (size_t)s0 * 64 + 2 * q;
            const float* hr0 = h_d + (size_t)rc0 * 64 + 2 * q;
            const float* hs1 = h_d + (size_t)s1 * 64 + 2 * q;
            const float* hr1 = h_d + (size_t)rc1 * 64 + 2 * q;
            float* ag0 = g_agg + (size_t)rc0 * 64 + 2 * q;
            float* ag1 = g_agg + (size_t)rc1 * 64 + 2 * q;
            #pragma unroll
            for (int j = 0; j < 8; j++) {
                float p00 = relu(c2[j][0]), p01 = relu(c2[j][1]);
                float p10 = relu(c2[j][2]), p11 = relu(c2[j][3]);
                float2 a = *(const float2*)(hs0 + 8 * j);
                float2 b = *(const float2*)(hr0 + 8 * j);
                float2 e = *(const float2*)(hs1 + 8 * j);
                float2 d = *(const float2*)(hr1 + 8 * j);
                if (p00 != 0.f) atomicAdd(ag0 + 8 * j,     p00 * (b.x - a.x));
                if (p01 != 0.f) atomicAdd(ag0 + 8 * j + 1, p01 * (b.y - a.y));
                if (p10 != 0.f) atomicAdd(ag1 + 8 * j,     p10 * (d.x - e.x));
                if (p11 != 0.f) atomicAdd(ag1 + 8 * j + 1, p11 * (d.y - e.y));
            }
        }
    }
}

// ---------------------------------------------------------------------------
// out = h_d_prev + agg @ Wm
__global__ __launch_bounds__(256) void out_kernel(
    const float* __restrict__ h_d, const float* __restrict__ Wm,
    float* __restrict__ out)
{
    __shared__ float wm[4096];
    __shared__ float ag[64 * 68];
    int tid = threadIdx.x;
    for (int i = tid; i < 1024; i += 256)
        ((float4*)wm)[i] = ((const float4*)Wm)[i];
    int base = blockIdx.x * 64;
    for (int i = tid; i < 1024; i += 256) {
        int r = i >> 4, q = i & 15;
        int n = base + r;
        float4 v = make_float4(0.f, 0.f, 0.f, 0.f);
        if (n < NN) v = *((const float4*)(g_agg + (size_t)n * 64 + q * 4));
        *((float4*)(ag + r * 68 + q * 4)) = v;
    }
    __syncthreads();

    int row = tid >> 2;
    int cb = (tid & 3) * 16;
    float acc[16];
    #pragma unroll
    for (int j = 0; j < 16; j++) acc[j] = 0.f;
    #pragma unroll 8
    for (int k = 0; k < 64; k++) {
        float a = ag[row * 68 + k];
        float w[16];
        *(float4*)&w[0]  = *(float4*)(wm + k * 64 + cb);
        *(float4*)&w[4]  = *(float4*)(wm + k * 64 + cb + 4);
        *(float4*)&w[8]  = *(float4*)(wm + k * 64 + cb + 8);
        *(float4*)&w[12] = *(float4*)(wm + k * 64 + cb + 12);
        #pragma unroll
        for (int j = 0; j < 16; j++) acc[j] += a * w[j];
    }
    int n = base + row;
    if (n < NN) {
        #pragma unroll
        for (int v4 = 0; v4 < 4; v4++) {
            float4 h = *((const float4*)(h_d + (size_t)n * 64 + cb + v4 * 4));
            float4 o = make_float4(acc[v4 * 4 + 0] + h.x, acc[v4 * 4 + 1] + h.y,
                                   acc[v4 * 4 + 2] + h.z, acc[v4 * 4 + 3] + h.w);
            *((float4*)(out + (size_t)n * 64 + cb + v4 * 4)) = o;
        }
    }
}

// ---------------------------------------------------------------------------
#define NODE_SMEM ((32768 + 8448) * 4)   // 164864 B

extern "C" void kernel_launch(void* const* d_in, const int* in_sizes, int n_in,
                              void* d_out, int out_size) {
    const float* h_d_prev  = (const float*)d_in[0];
    const float* h_s       = (const float*)d_in[1];
    const float* edge_feat = (const float*)d_in[2];
    const int*   sender    = (const int*)d_in[3];
    const int*   receiver  = (const int*)d_in[4];
    const float* W0        = (const float*)d_in[5];
    const float* b0        = (const float*)d_in[6];
    const float* W1        = (const float*)d_in[7];
    const float* b1        = (const float*)d_in[8];
    const float* W2        = (const float*)d_in[9];
    const float* b2        = (const float*)d_in[10];
    const float* Wm        = (const float*)d_in[11];
    float* out = (float*)d_out;

    (void)cudaFuncSetAttribute(node_pre_kernel,
                               cudaFuncAttributeMaxDynamicSharedMemorySize, NODE_SMEM);
    (void)cudaFuncSetAttribute(edge_kernel,
                               cudaFuncAttributeMaxDynamicSharedMemorySize, EDGE_SMEM);

    zero_agg_kernel<<<(NN * 64 + 511) / 512, 512>>>();
    node_pre_kernel<<<(NN + 63) / 64, 512, NODE_SMEM>>>(h_s, h_d_prev, W0, b0);
    edge_kernel<<<148, 256, EDGE_SMEM>>>(edge_feat, sender, receiver, h_d_prev,
                                         W0, W1, b1, W2, b2);
    out_kernel<<<(NN + 63) / 64, 256>>>(h_d_prev, Wm, out);
}